// round 17
// baseline (speedup 1.0000x reference)
#include <cuda_runtime.h>
#include <cuda_bf16.h>
#include <cstdint>

#define SEQ    2048
#define BATCH  512
#define INPT   64
#define HIDDEN 128
#define BB     4
#define NBLK   (BATCH / BB)    // 128 blocks, 1/SM
#define NTHR   384             // 8 consumer warps + 4 producer warps
#define NKT    8               // consumer k-tiles (K = HIDDEN = 128)
#define NS     4               // xp ring slots

__device__ __forceinline__ float tanh_fast(float z) {
    float az = fabsf(z);
    float e  = __expf(-2.0f * az);
    float r  = __fdividef(1.0f - e, 1.0f + e);
    return copysignf(r, z);
}
__device__ __forceinline__ void cp16(void* smem_dst, const float* gsrc) {
    unsigned dst = (unsigned)__cvta_generic_to_shared(smem_dst);
    asm volatile("cp.async.ca.shared.global [%0], [%1], 16;" :: "r"(dst), "l"(gsrc));
}
__device__ __forceinline__ void split_bf(float v, __nv_bfloat16& hi,
                                         __nv_bfloat16& lo) {
    hi = __float2bfloat16(v);
    lo = __float2bfloat16(v - __bfloat162float(hi));
}
__device__ __forceinline__ uint32_t pack2bf(__nv_bfloat16 a, __nv_bfloat16 b) {
    __nv_bfloat162 t(a, b);                 // a -> low 16 bits
    return *reinterpret_cast<uint32_t*>(&t);
}
__device__ __forceinline__ void mma16816(float* d, const uint32_t* a,
                                         uint32_t b0, uint32_t b1) {
    asm volatile(
        "mma.sync.aligned.m16n8k16.row.col.f32.bf16.bf16.f32 "
        "{%0,%1,%2,%3}, {%4,%5,%6,%7}, {%8,%9}, {%0,%1,%2,%3};"
        : "+f"(d[0]), "+f"(d[1]), "+f"(d[2]), "+f"(d[3])
        : "r"(a[0]), "r"(a[1]), "r"(a[2]), "r"(a[3]), "r"(b0), "r"(b1));
}
// load one m16n8k16 A-fragment pair (hi/lo) from a weight row pair
__device__ __forceinline__ void load_afrag(const float* W, int ld, int j0,
                                           int j1, int c0, uint32_t* aH,
                                           uint32_t* aL) {
    float w00 = W[j0 * ld + c0],     w01 = W[j0 * ld + c0 + 1];
    float w10 = W[j1 * ld + c0],     w11 = W[j1 * ld + c0 + 1];
    float w02 = W[j0 * ld + c0 + 8], w03 = W[j0 * ld + c0 + 9];
    float w12 = W[j1 * ld + c0 + 8], w13 = W[j1 * ld + c0 + 9];
    __nv_bfloat16 h, l, h2, l2;
    split_bf(w00, h, l); split_bf(w01, h2, l2);
    aH[0] = pack2bf(h, h2); aL[0] = pack2bf(l, l2);
    split_bf(w10, h, l); split_bf(w11, h2, l2);
    aH[1] = pack2bf(h, h2); aL[1] = pack2bf(l, l2);
    split_bf(w02, h, l); split_bf(w03, h2, l2);
    aH[2] = pack2bf(h, h2); aL[2] = pack2bf(l, l2);
    split_bf(w12, h, l); split_bf(w13, h2, l2);
    aH[3] = pack2bf(h, h2); aL[3] = pack2bf(l, l2);
}

__global__ void __launch_bounds__(NTHR, 1)
rnn_pc_kernel(const float* __restrict__ xs,
              const float* __restrict__ W_ih,
              const float* __restrict__ W_hh,
              const float* __restrict__ b_ih,
              const float* __restrict__ b_hh,
              const float* __restrict__ W_out,
              const float* __restrict__ b_out,
              float* __restrict__ out) {
    __shared__ uint32_t uHi[2][64 * 8];            // consumer h (bf16 hi)
    __shared__ uint32_t uLo[2][64 * 8];            // consumer h (bf16 lo)
    __shared__ float ring[NS][BB][HIDDEN];         // xp ring (8 KB)
    __shared__ uint32_t pxh[32 * 8], pxl[32 * 8];  // producer converted x
    __shared__ __align__(16) float stg[NS][BB][INPT];  // producer x stage
    __shared__ float red[BB][HIDDEN];
    __shared__ int prodS[NS], consS[NS];           // slot stamps

    const int tid = threadIdx.x;
    const long bbase = (long)blockIdx.x * BB;

    // ---- common init ----
    for (int i = tid; i < 2 * 64 * 8; i += NTHR) {
        (&uHi[0][0])[i] = 0u;
        (&uLo[0][0])[i] = 0u;
    }
    for (int i = tid; i < 32 * 8; i += NTHR) { pxh[i] = 0u; pxl[i] = 0u; }
    if (tid < NS) { prodS[tid] = 0; consS[tid] = 0; }
    __syncthreads();   // only block-wide barrier in the kernel

    if (tid < 256) {
        // ===================== CONSUMER (warps 0-7) =====================
        const int wid  = tid >> 5;
        const int lane = tid & 31;
        const int g    = lane >> 2;
        const int q    = lane & 3;
        const int jr0  = 16 * wid + g;
        const int jr1  = jr0 + 8;
        const bool act = (q < 2);
        const int b0n  = 2 * q;

        uint32_t aH[NKT][4], aL[NKT][4];
        #pragma unroll
        for (int kt = 0; kt < NKT; kt++)
            load_afrag(W_hh, HIDDEN, jr0, jr1, kt * 16 + 2 * q, aH[kt], aL[kt]);

        const int hidx = ((jr0 >> 1) * 8 + b0n) * 2 + (jr0 & 1);
        volatile int*   vp = prodS;
        volatile float* vr = &ring[0][0][0];

        for (int t = 0; t < SEQ - 1; ++t) {
            const int cur = t & 1, nxt = cur ^ 1, s = t & (NS - 1);

            float D1[4] = {0, 0, 0, 0}, D2[4] = {0, 0, 0, 0}, D3[4] = {0, 0, 0, 0};
            #pragma unroll
            for (int kt = 0; kt < NKT; kt++) {
                int wi = (kt * 8 + q) * 8 + g;
                uint32_t bh0 = uHi[cur][wi], bh1 = uHi[cur][wi + 32];
                uint32_t bl0 = uLo[cur][wi], bl1 = uLo[cur][wi + 32];
                mma16816(D1, aH[kt], bh0, bh1);
                mma16816(D2, aL[kt], bh0, bh1);
                mma16816(D3, aH[kt], bl0, bl1);
            }

            while (vp[s] < t + 1) { }   // xp(t) ready? (normally yes)

            if (act) {
                int rbase = (s * BB + b0n) * HIDDEN;
                float xp00 = vr[rbase + jr0];
                float xp01 = vr[rbase + HIDDEN + jr0];
                float xp10 = vr[rbase + jr1];
                float xp11 = vr[rbase + HIDDEN + jr1];
                float h00 = tanh_fast(D1[0] + D2[0] + D3[0] + xp00);
                float h01 = tanh_fast(D1[1] + D2[1] + D3[1] + xp01);
                float h10 = tanh_fast(D1[2] + D2[2] + D3[2] + xp10);
                float h11 = tanh_fast(D1[3] + D2[3] + D3[3] + xp11);
                __nv_bfloat16* phN = reinterpret_cast<__nv_bfloat16*>(&uHi[nxt][0]);
                __nv_bfloat16* plN = reinterpret_cast<__nv_bfloat16*>(&uLo[nxt][0]);
                __nv_bfloat16 hh, ll;
                split_bf(h00, hh, ll); phN[hidx]      = hh; plN[hidx]      = ll;
                split_bf(h01, hh, ll); phN[hidx + 2]  = hh; plN[hidx + 2]  = ll;
                split_bf(h10, hh, ll); phN[hidx + 64] = hh; plN[hidx + 64] = ll;
                split_bf(h11, hh, ll); phN[hidx + 66] = hh; plN[hidx + 66] = ll;
            }
            asm volatile("bar.sync 1, 256;" ::: "memory");
            if (tid == 0) ((volatile int*)consS)[s] = (t >> 2) + 1;
        }

        // peeled final step
        {
            const int t = SEQ - 1, cur = t & 1, s = t & (NS - 1);
            float D1[4] = {0, 0, 0, 0}, D2[4] = {0, 0, 0, 0}, D3[4] = {0, 0, 0, 0};
            #pragma unroll
            for (int kt = 0; kt < NKT; kt++) {
                int wi = (kt * 8 + q) * 8 + g;
                uint32_t bh0 = uHi[cur][wi], bh1 = uHi[cur][wi + 32];
                uint32_t bl0 = uLo[cur][wi], bl1 = uLo[cur][wi + 32];
                mma16816(D1, aH[kt], bh0, bh1);
                mma16816(D2, aL[kt], bh0, bh1);
                mma16816(D3, aH[kt], bl0, bl1);
            }
            while (vp[s] < t + 1) { }
            if (act) {
                int rbase = (s * BB + b0n) * HIDDEN;
                red[b0n][jr0]     = tanh_fast(D1[0] + D2[0] + D3[0] + vr[rbase + jr0]);
                red[b0n + 1][jr0] = tanh_fast(D1[1] + D2[1] + D3[1] + vr[rbase + HIDDEN + jr0]);
                red[b0n][jr1]     = tanh_fast(D1[2] + D2[2] + D3[2] + vr[rbase + jr1]);
                red[b0n + 1][jr1] = tanh_fast(D1[3] + D2[3] + D3[3] + vr[rbase + HIDDEN + jr1]);
            }
            asm volatile("bar.sync 1, 256;" ::: "memory");
        }

        // output projection
        if (wid < BB) {
            int b = wid;
            float s = 0.0f;
            #pragma unroll
            for (int m = 0; m < 4; m++) {
                int jj = lane + 32 * m;
                s += red[b][jj] * W_out[jj];
            }
            #pragma unroll
            for (int off = 16; off; off >>= 1)
                s += __shfl_down_sync(0xffffffffu, s, off);
            if (lane == 0) out[bbase + b] = s + b_out[0];
        }
    } else {
        // ===================== PRODUCER (warps 8-11) =====================
        const int ptid  = tid - 256;
        const int pwid  = ptid >> 5;
        const int plane = ptid & 31;
        const int g     = plane >> 2;
        const int q     = plane & 3;

        // two j-tiles per warp: a = [32p, 32p+16), b = [32p+16, 32p+32)
        const int jA0 = 32 * pwid + g,  jA1 = jA0 + 8;
        const int jB0 = jA0 + 16,       jB1 = jB0 + 8;

        uint32_t aHa[4][4], aLa[4][4], aHb[4][4], aLb[4][4];
        #pragma unroll
        for (int kt = 0; kt < 4; kt++) {
            load_afrag(W_ih, INPT, jA0, jA1, kt * 16 + 2 * q, aHa[kt], aLa[kt]);
            load_afrag(W_ih, INPT, jB0, jB1, kt * 16 + 2 * q, aHb[kt], aLb[kt]);
        }
        const float bA0 = b_ih[jA0] + b_hh[jA0];
        const float bA1 = b_ih[jA1] + b_hh[jA1];
        const float bB0 = b_ih[jB0] + b_hh[jB0];
        const float bB1 = b_ih[jB1] + b_hh[jB1];

        const int nC  = ptid & 3;       // converter batch
        const int kpC = ptid >> 2;      // converter k-pair [0,32)

        // prologue: stage x(0..3), one commit group each
        #pragma unroll
        for (int ss = 0; ss < NS; ss++) {
            if (ptid < 64) {
                int b = ptid >> 4, seg = ptid & 15;
                cp16(&stg[ss][b][seg * 4],
                     xs + ((long)ss * BATCH + bbase + b) * INPT + seg * 4);
            }
            asm volatile("cp.async.commit_group;" ::);
        }

        volatile int* vc = consS;
        for (int t = 0; t < SEQ; ++t) {
            const int s = t & (NS - 1), r = t >> 2;
            while (vc[s] < r) { }                    // slot free?
            asm volatile("cp.async.wait_group 3;" ::);   // x(t) staged

            // convert x(t) -> px (hi/lo)
            {
                const float* sp = &stg[s][nC][2 * kpC];
                float x0 = sp[0], x1 = sp[1];
                __nv_bfloat16 h0, l0, h1, l1;
                split_bf(x0, h0, l0); split_bf(x1, h1, l1);
                pxh[kpC * 8 + nC] = pack2bf(h0, h1);
                pxl[kpC * 8 + nC] = pack2bf(l0, l1);
            }
            asm volatile("bar.sync 2, 128;" ::: "memory");

            // prefetch x(t+4) into the just-freed stage slot
            if (t + 4 < SEQ && ptid < 64) {
                int b = ptid >> 4, seg = ptid & 15;
                cp16(&stg[s][b][seg * 4],
                     xs + ((long)(t + 4) * BATCH + bbase + b) * INPT + seg * 4);
            }
            asm volatile("cp.async.commit_group;" ::);

            // 24 HMMA: both tiles, 3 terms
            float Da1[4] = {0,0,0,0}, Da2[4] = {0,0,0,0}, Da3[4] = {0,0,0,0};
            float Db1[4] = {0,0,0,0}, Db2[4] = {0,0,0,0}, Db3[4] = {0,0,0,0};
            #pragma unroll
            for (int kt = 0; kt < 4; kt++) {
                int wi = (kt * 8 + q) * 8 + g;
                uint32_t bh0 = pxh[wi], bh1 = pxh[wi + 32];
                uint32_t bl0 = pxl[wi], bl1 = pxl[wi + 32];
                mma16816(Da1, aHa[kt], bh0, bh1);
                mma16816(Da2, aLa[kt], bh0, bh1);
                mma16816(Da3, aHa[kt], bl0, bl1);
                mma16816(Db1, aHb[kt], bh0, bh1);
                mma16816(Db2, aLb[kt], bh0, bh1);
                mma16816(Db3, aHb[kt], bl0, bl1);
            }

            if (q < 2) {
                float* rs = &ring[s][0][0];
                int c0 = 2 * q;
                rs[c0 * HIDDEN + jA0]       = Da1[0] + Da2[0] + Da3[0] + bA0;
                rs[(c0 + 1) * HIDDEN + jA0] = Da1[1] + Da2[1] + Da3[1] + bA0;
                rs[c0 * HIDDEN + jA1]       = Da1[2] + Da2[2] + Da3[2] + bA1;
                rs[(c0 + 1) * HIDDEN + jA1] = Da1[3] + Da2[3] + Da3[3] + bA1;
                rs[c0 * HIDDEN + jB0]       = Db1[0] + Db2[0] + Db3[0] + bB0;
                rs[(c0 + 1) * HIDDEN + jB0] = Db1[1] + Db2[1] + Db3[1] + bB0;
                rs[c0 * HIDDEN + jB1]       = Db1[2] + Db2[2] + Db3[2] + bB1;
                rs[(c0 + 1) * HIDDEN + jB1] = Db1[3] + Db2[3] + Db3[3] + bB1;
            }
            asm volatile("bar.sync 2, 128;" ::: "memory");   // drains STS
            if (ptid == 0) ((volatile int*)prodS)[s] = t + 1;
        }
    }
}

extern "C" void kernel_launch(void* const* d_in, const int* in_sizes, int n_in,
                              void* d_out, int out_size) {
    const float* xs    = (const float*)d_in[0];
    const float* W_ih  = (const float*)d_in[1];
    const float* W_hh  = (const float*)d_in[2];
    const float* b_ih  = (const float*)d_in[3];
    const float* b_hh  = (const float*)d_in[4];
    const float* W_out = (const float*)d_in[5];
    const float* b_out = (const float*)d_in[6];

    rnn_pc_kernel<<<NBLK, NTHR>>>(xs, W_ih, W_hh, b_ih, b_hh, W_out, b_out,
                                  (float*)d_out);
}